// round 5
// baseline (speedup 1.0000x reference)
#include <cuda_runtime.h>

#define GDIM 7
#define GG 49
#define NWARPS 8             // warps per block; each warp does 2 samples
#define SPW 2                // samples per warp

__device__ double   g_acc   = 0.0;
__device__ unsigned g_count = 0u;

__global__ void __launch_bounds__(32 * NWARPS, 5)
loss_fused_kernel(const float* __restrict__ bboxp,   // (N,15,7,7)
                  const float* __restrict__ clsp,    // (N,2)
                  const float* __restrict__ bbox,    // (N,5,7,7)
                  const int*   __restrict__ cls32,   // (N,) int64 viewed as int32 pairs
                  float* __restrict__ out,
                  int N)
{
    const unsigned FULL = 0xffffffffu;
    const int warp = threadIdx.x >> 5;
    const int l    = threadIdx.x & 31;
    const int b0   = (blockIdx.x * NWARPS + warp) * SPW;
    const bool hi  = (l < GG - 32);                  // l < 17

    float tot = 0.0f;

    if (b0 + SPW <= N) {
        // ---------- phase 1: issue ALL channel loads for both samples ----------
        float p0[SPW], p1[SPW];
        float q0a[SPW], q0b[SPW], q0c[SPW], q1a[SPW], q1b[SPW], q1c[SPW];
        #pragma unroll
        for (int k = 0; k < SPW; k++) {
            const float* bb = bbox  + (size_t)(b0 + k) * (5 * GG);
            const float* bp = bboxp + (size_t)(b0 + k) * (15 * GG);
            p0[k]  = bb[l];
            p1[k]  = hi ? bb[l + 32] : 0.0f;
            q0a[k] = bp[l];          q1a[k] = hi ? bp[l + 32]         : 0.5f;
            q0b[k] = bp[5*GG + l];   q1b[k] = hi ? bp[5*GG + l + 32]  : 0.5f;
            q0c[k] = bp[10*GG + l];  q1c[k] = hi ? bp[10*GG + l + 32] : 0.5f;
        }
        float c0 = 0.f, c1 = 0.f, c2 = 0.f, c3 = 0.f; int y0 = 1, y1 = 1;
        if (l == 0) {
            c0 = clsp[2 * (size_t)b0];     c1 = clsp[2 * (size_t)b0 + 1];
            c2 = clsp[2 * (size_t)b0 + 2]; c3 = clsp[2 * (size_t)b0 + 3];
            y0 = cls32[2 * b0];            y1 = cls32[2 * b0 + 2];
        }

        // ---------- phase 2: argmax for both samples, then both gathers ----------
        int m[SPW];
        #pragma unroll
        for (int k = 0; k < SPW; k++) {
            const unsigned w0 = __float_as_uint(p0[k]);          // probs > 0
            const unsigned w1 = hi ? __float_as_uint(p1[k]) : 0u;
            const unsigned vmax = __reduce_max_sync(FULL, w0 > w1 ? w0 : w1);
            const unsigned bal0 = __ballot_sync(FULL, w0 == vmax);
            const unsigned bal1 = __ballot_sync(FULL, w1 == vmax);
            m[k] = bal0 ? (__ffs(bal0) - 1) : (32 + __ffs(bal1) - 1);
        }
        float g[SPW];
        #pragma unroll
        for (int k = 0; k < SPW; k++) {
            const float* bb = bbox  + (size_t)(b0 + k) * (5 * GG);
            const float* bp = bboxp + (size_t)(b0 + k) * (15 * GG);
            float gv = 0.0f;
            if (l < 15)      gv = bp[l * GG + m[k]];             // cell_pr ch 0..14
            else if (l < 19) gv = bb[(l - 14) * GG + m[k]];      // cell_gt ch 1..4
            g[k] = gv;
        }

        // ---------- phase 3: per-sample math ----------
        #pragma unroll
        for (int k = 0; k < SPW; k++) {
            const float jf  = (float)(m[k] % GDIM);
            const float if_ = (float)(m[k] / GDIM);

            // log-of-product for sum of -log(1-q)
            float P = (1.0f - q0a[k]) * (1.0f - q0b[k]) * (1.0f - q0c[k]);
            if (hi) P *= (1.0f - q1a[k]) * (1.0f - q1b[k]) * (1.0f - q1c[k]);
            float s = -__logf(P);

            // broadcast gt; lanes 0..2 own one anchor each
            const float gt1 = __shfl_sync(FULL, g[k], 15);
            const float gt2 = __shfl_sync(FULL, g[k], 16);
            const float gt3 = __shfl_sync(FULL, g[k], 17);
            const float gt4 = __shfl_sync(FULL, g[k], 18);
            const int   al  = 5 * min(l, 2);
            const float a1  = __shfl_sync(FULL, g[k], al + 1);
            const float a2  = __shfl_sync(FULL, g[k], al + 2);
            const float a3  = __shfl_sync(FULL, g[k], al + 3);
            const float a4  = __shfl_sync(FULL, g[k], al + 4);

            // IoU on lanes 0..2, winner via packed REDUX (first-index ties)
            const float inv7 = 1.0f / 7.0f;
            const float tx  = (gt1 + jf)  * inv7;
            const float ty  = (gt2 + if_) * inv7;
            const float tx1 = tx - gt3 * 0.5f, tx2 = tx + gt3 * 0.5f;
            const float ty1 = ty - gt4 * 0.5f, ty2 = ty + gt4 * 0.5f;
            const float tarea = (tx2 - tx1) * (ty2 - ty1);

            const float ax  = (a1 + jf)  * inv7;
            const float ay  = (a2 + if_) * inv7;
            const float ax1 = ax - a3 * 0.5f, ax2 = ax + a3 * 0.5f;
            const float ay1 = ay - a4 * 0.5f, ay2 = ay + a4 * 0.5f;
            float iw = fmaxf(fminf(ax2, tx2) - fmaxf(ax1, tx1), 0.0f);
            float ih = fmaxf(fminf(ay2, ty2) - fmaxf(ay1, ty1), 0.0f);
            float inter = iw * ih;
            float uni   = (ax2 - ax1) * (ay2 - ay1) + tarea - inter;
            float iou   = __fdividef(inter, uni + 1e-9f);

            unsigned key = (l < 3) ? ((__float_as_uint(iou) & ~3u) | (3u - l)) : 0u;
            key = __reduce_max_sync(FULL, key);
            const int best = 3 - (int)(key & 3u);

            // BCE correction for best anchor: -p * (log q - log(1-q))
            float qb0 = (best == 0) ? q0a[k] : (best == 1) ? q0b[k] : q0c[k];
            s -= p0[k] * (__logf(qb0) - __logf(1.0f - qb0));
            if (hi) {
                float qb1 = (best == 0) ? q1a[k] : (best == 1) ? q1b[k] : q1c[k];
                s -= p1[k] * (__logf(qb1) - __logf(1.0f - qb1));
            }

            float t = s * (1.0f / ((float)N * 49.0f));

            // coord + size on the winning anchor's lane (it holds a1..a4)
            if (l == best) {
                float coord = -(gt1 * __logf(a1) + (1.0f - gt1) * __logf(1.0f - a1))
                            + -(gt2 * __logf(a2) + (1.0f - gt2) * __logf(1.0f - a2));
                float size_ = fabsf(__logf(a3) - __logf(gt3))
                            + fabsf(__logf(a4) - __logf(gt4));
                t += coord + size_;
            }
            // CE on lane 0
            if (l == 0) {
                float e0 = (k == 0) ? c0 : c2;
                float e1 = (k == 0) ? c1 : c3;
                int   yy = (k == 0) ? y0 : y1;
                float mx  = fmaxf(e0, e1);
                float lse = mx + __logf(__expf(e0 - mx) + __expf(e1 - mx));
                float sel = (yy == 1) ? e0 : e1;
                t += (lse - sel) * (1.0f / (float)N);
            }
            tot += t;
        }
    }

    // ---- warp reduce ----
    #pragma unroll
    for (int off = 16; off; off >>= 1)
        tot += __shfl_xor_sync(FULL, tot, off);

    // ---- block reduce -> one double atomic per block ----
    __shared__ float wsum[NWARPS];
    if (l == 0) wsum[warp] = tot;
    __syncthreads();
    if (threadIdx.x == 0) {
        float x = 0.0f;
        #pragma unroll
        for (int w = 0; w < NWARPS; w++) x += wsum[w];
        atomicAdd(&g_acc, (double)x);
        __threadfence();
        unsigned old = atomicInc(&g_count, gridDim.x - 1);
        if (old == gridDim.x - 1) {
            unsigned long long raw =
                atomicExch((unsigned long long*)&g_acc, 0ull);
            out[0] = (float)__longlong_as_double(raw);
        }
    }
}

extern "C" void kernel_launch(void* const* d_in, const int* in_sizes, int n_in,
                              void* d_out, int out_size)
{
    const float* bboxp = (const float*)d_in[0];     // (N,15,7,7)
    const float* clsp  = (const float*)d_in[1];     // (N,2)
    const float* bbox  = (const float*)d_in[2];     // (N,5,7,7)
    const int*   cls32 = (const int*)d_in[3];       // (N,) int64 -> int32 pairs

    const int N = in_sizes[3];
    const int nblocks = (N + NWARPS * SPW - 1) / (NWARPS * SPW);

    loss_fused_kernel<<<nblocks, 32 * NWARPS>>>(bboxp, clsp, bbox, cls32,
                                                (float*)d_out, N);
}